// round 2
// baseline (speedup 1.0000x reference)
#include <cuda_runtime.h>
#include <cstdint>

#define T_MAX 8192
#define K_IN  4096
#define N_OUT 4096
#define RANK  8
#define KSPLIT 4

#define BM 128
#define BN 128
#define BK 64
#define SROW 80   // padded smem row stride (bytes): conflict-free frag loads

// Scratch (no allocations allowed)
__device__ int8_t g_xq[(size_t)T_MAX * K_IN];
__device__ float  g_xs[T_MAX];
__device__ float  g_xa[(size_t)KSPLIT * T_MAX * RANK];
__device__ int8_t g_w8[(size_t)N_OUT * K_IN];
__device__ int    g_wmode;   // 1 = weights delivered as int32, 0 = packed int8

// ---------------------------------------------------------------------------
// Kernel 0a: detect weight buffer dtype (int32-promoted vs packed int8).
// int32-mode: every word is a weight value in [-127,127]. Packed int8 words
// look like 4 random bytes -> virtually never all small for 4096 words.
// ---------------------------------------------------------------------------
__global__ void detect_kernel(const int* __restrict__ w) {
    __shared__ int ok_s;
    if (threadIdx.x == 0) ok_s = 1;
    __syncthreads();
    int v = w[threadIdx.x + blockIdx.x * blockDim.x];
    if (v < -200 || v > 200) atomicAnd(&ok_s, 0);
    __syncthreads();
    if (threadIdx.x == 0 && ok_s == 0) atomicAnd(&g_wmode, 0);
}
__global__ void detect_init_kernel() { g_wmode = 1; }

// Kernel 0b: pack weights into contiguous int8
__global__ __launch_bounds__(256) void pack_kernel(const void* __restrict__ w) {
    size_t gid = (size_t)blockIdx.x * 256 + threadIdx.x;   // one char4 per thread
    if (g_wmode) {
        int4 v = ((const int4*)w)[gid];
        ((char4*)g_w8)[gid] = make_char4((signed char)v.x, (signed char)v.y,
                                         (signed char)v.z, (signed char)v.w);
    } else {
        ((char4*)g_w8)[gid] = ((const char4*)w)[gid];
    }
}

// ---------------------------------------------------------------------------
// Kernel 1: row-wise symmetric int8 quantization of x
// ---------------------------------------------------------------------------
__global__ __launch_bounds__(256) void quant_kernel(const float* __restrict__ x) {
    int row = blockIdx.x;
    int tid = threadIdx.x;
    const float4* xr = (const float4*)(x + (size_t)row * K_IN);
    float4 v[4];
    float m = 0.f;
#pragma unroll
    for (int i = 0; i < 4; i++) {
        v[i] = xr[tid + 256 * i];
        m = fmaxf(m, fmaxf(fmaxf(fabsf(v[i].x), fabsf(v[i].y)),
                           fmaxf(fabsf(v[i].z), fabsf(v[i].w))));
    }
    __shared__ float red[8];
#pragma unroll
    for (int o = 16; o > 0; o >>= 1) m = fmaxf(m, __shfl_xor_sync(0xffffffffu, m, o));
    if ((tid & 31) == 0) red[tid >> 5] = m;
    __syncthreads();
    if (tid < 32) {
        float mm = (tid < 8) ? red[tid] : 0.f;
#pragma unroll
        for (int o = 4; o > 0; o >>= 1) mm = fmaxf(mm, __shfl_xor_sync(0xffffffffu, mm, o));
        if (tid == 0) red[0] = mm;
    }
    __syncthreads();
    m = red[0];
    float scale = m * (1.0f / 127.0f);     // unclipped scale (what reference stores)
    float sc    = fmaxf(scale, 1e-12f);    // clipped for division
    float inv   = 1.0f / sc;
    if (tid == 0) g_xs[row] = scale;

    char4* qr = (char4*)(g_xq + (size_t)row * K_IN);
#pragma unroll
    for (int i = 0; i < 4; i++) {
        int qx = __float2int_rn(v[i].x * inv);
        int qy = __float2int_rn(v[i].y * inv);
        int qz = __float2int_rn(v[i].z * inv);
        int qw = __float2int_rn(v[i].w * inv);
        qx = max(-127, min(127, qx)); qy = max(-127, min(127, qy));
        qz = max(-127, min(127, qz)); qw = max(-127, min(127, qw));
        qr[tid + 256 * i] = make_char4((signed char)qx, (signed char)qy,
                                       (signed char)qz, (signed char)qw);
    }
}

// ---------------------------------------------------------------------------
// Kernel 2: xa_part[ks] = x[:, ks-slice] @ A[:, ks-slice]^T   (k-split)
// ---------------------------------------------------------------------------
__global__ __launch_bounds__(256) void lora_a_kernel(const float* __restrict__ x,
                                                     const float* __restrict__ A) {
    int row = blockIdx.x * 256 + threadIdx.x;
    int ks  = blockIdx.y;
    const int KC = K_IN / KSPLIT;            // 1024
    const float4* xr = (const float4*)(x + (size_t)row * K_IN + (size_t)ks * KC);
    float acc[RANK];
#pragma unroll
    for (int r = 0; r < RANK; r++) acc[r] = 0.f;

    const int J = KC / 4;                    // 256
#pragma unroll 4
    for (int j = 0; j < J; j++) {
        float4 xv = xr[j];
        int k = ks * KC + j * 4;
#pragma unroll
        for (int r = 0; r < RANK; r++) {
            float4 av = *(const float4*)(A + (size_t)r * K_IN + k);
            acc[r] = fmaf(xv.x, av.x, acc[r]);
            acc[r] = fmaf(xv.y, av.y, acc[r]);
            acc[r] = fmaf(xv.z, av.z, acc[r]);
            acc[r] = fmaf(xv.w, av.w, acc[r]);
        }
    }
    float* dst = g_xa + ((size_t)ks * T_MAX + row) * RANK;
#pragma unroll
    for (int r = 0; r < RANK; r++) dst[r] = acc[r];
}

// ---------------------------------------------------------------------------
// Kernel 3: int8 GEMM (IMMA m16n8k32) + fused dequant + LoRA-B epilogue
// ---------------------------------------------------------------------------
__device__ __forceinline__ void cp_async16(uint32_t dst, const void* src) {
    asm volatile("cp.async.cg.shared.global [%0], [%1], 16;\n" :: "r"(dst), "l"(src));
}
__device__ __forceinline__ void mma_s8(int* c, const uint32_t* a, const uint32_t* b) {
    asm volatile(
        "mma.sync.aligned.m16n8k32.row.col.s32.s8.s8.s32 "
        "{%0,%1,%2,%3}, {%4,%5,%6,%7}, {%8,%9}, {%0,%1,%2,%3};"
        : "+r"(c[0]), "+r"(c[1]), "+r"(c[2]), "+r"(c[3])
        : "r"(a[0]), "r"(a[1]), "r"(a[2]), "r"(a[3]), "r"(b[0]), "r"(b[1]));
}

__global__ __launch_bounds__(256, 2)
void gemm_kernel(const float* __restrict__ wscale,
                 const float* __restrict__ lora_b,
                 float* __restrict__ out) {
    __shared__ __align__(16) char smem[2 * BM * SROW + 2 * BN * SROW]; // 40960 B
    char* sA = smem;
    char* sB = smem + 2 * BM * SROW;

    int tid  = threadIdx.x;
    int wid  = tid >> 5;
    int lane = tid & 31;
    int gid  = lane >> 2;     // 0..7
    int tid4 = lane & 3;      // 0..3
    int wm = wid & 1;         // 2 warps along M (64 rows each)
    int wn = wid >> 1;        // 4 warps along N (32 cols each)
    int bm = blockIdx.y, bn = blockIdx.x;

    const int8_t* Aglob = g_xq + (size_t)(bm * BM) * K_IN;
    const int8_t* Bglob = g_w8 + (size_t)(bn * BN) * K_IN;

    uint32_t sA_u = (uint32_t)__cvta_generic_to_shared(sA);
    uint32_t sB_u = (uint32_t)__cvta_generic_to_shared(sB);

    int c[4][4][4];
#pragma unroll
    for (int mf = 0; mf < 4; mf++)
#pragma unroll
        for (int nf = 0; nf < 4; nf++)
#pragma unroll
            for (int i = 0; i < 4; i++) c[mf][nf][i] = 0;

#define LOAD_TILE(kt, buf)                                                        \
    {                                                                             \
        int _k0 = (kt) * BK;                                                      \
        _Pragma("unroll")                                                         \
        for (int _u = 0; _u < 2; _u++) {                                          \
            int _idx = tid + 256 * _u;                                            \
            int _row = _idx >> 2;                                                 \
            int _ch  = (_idx & 3) * 16;                                           \
            cp_async16(sA_u + (buf) * (BM * SROW) + _row * SROW + _ch,            \
                       Aglob + (size_t)_row * K_IN + _k0 + _ch);                  \
            cp_async16(sB_u + (buf) * (BN * SROW) + _row * SROW + _ch,            \
                       Bglob + (size_t)_row * K_IN + _k0 + _ch);                  \
        }                                                                         \
        asm volatile("cp.async.commit_group;\n");                                 \
    }

    LOAD_TILE(0, 0);
    asm volatile("cp.async.wait_group 0;\n");
    __syncthreads();

    const int NK = K_IN / BK;  // 64
    for (int kt = 0; kt < NK; kt++) {
        int buf = kt & 1;
        if (kt + 1 < NK) LOAD_TILE(kt + 1, buf ^ 1);

        const char* a_base = sA + buf * (BM * SROW) + (wm * 64) * SROW;
        const char* b_base = sB + buf * (BN * SROW) + (wn * 32) * SROW;
#pragma unroll
        for (int ks = 0; ks < 2; ks++) {
            int ko = ks * 32;
            uint32_t a[4][4];
#pragma unroll
            for (int mf = 0; mf < 4; mf++)
#pragma unroll
                for (int i = 0; i < 4; i++) {
                    int rr = mf * 16 + gid + (i & 1) * 8;
                    int kk = ko + (i >> 1) * 16 + tid4 * 4;
                    a[mf][i] = *(const uint32_t*)(a_base + rr * SROW + kk);
                }
            uint32_t b[4][2];
#pragma unroll
            for (int nf = 0; nf < 4; nf++)
#pragma unroll
                for (int j = 0; j < 2; j++) {
                    int rr = nf * 8 + gid;
                    int kk = ko + j * 16 + tid4 * 4;
                    b[nf][j] = *(const uint32_t*)(b_base + rr * SROW + kk);
                }
#pragma unroll
            for (int mf = 0; mf < 4; mf++)
#pragma unroll
                for (int nf = 0; nf < 4; nf++)
                    mma_s8(c[mf][nf], a[mf], b[nf]);
        }
        asm volatile("cp.async.wait_group 0;\n");
        __syncthreads();
    }

    // --- epilogue: reuse smem for scales + LoRA operands ---
    float* s_xs = (float*)smem;            // [BM]
    float* s_ws = s_xs + BM;               // [BN]
    float* s_xa = s_ws + BN;               // [BM*RANK]
    float* s_lb = s_xa + BM * RANK;        // [BN*RANK]

    if (tid < BM) s_xs[tid] = g_xs[bm * BM + tid];
    if (tid < BN) s_ws[tid] = wscale[bn * BN + tid];
    for (int i = tid; i < BM * RANK; i += 256) {
        int rl = i >> 3, r = i & 7;
        float s = 0.f;
#pragma unroll
        for (int p = 0; p < KSPLIT; p++)
            s += g_xa[((size_t)p * T_MAX + bm * BM + rl) * RANK + r];
        s_xa[i] = s;
    }
    for (int i = tid; i < BN * RANK; i += 256)
        s_lb[i] = lora_b[(size_t)(bn * BN) * RANK + i];
    __syncthreads();

    const float lscale = 1.0f;  // ALPHA / RANK = 8/8
#pragma unroll
    for (int mf = 0; mf < 4; mf++) {
#pragma unroll
        for (int nf = 0; nf < 4; nf++) {
            int rl0 = wm * 64 + mf * 16 + gid;
            int cl  = wn * 32 + nf * 8 + tid4 * 2;
            float ws0 = s_ws[cl], ws1 = s_ws[cl + 1];
#pragma unroll
            for (int h = 0; h < 2; h++) {
                int rl = rl0 + h * 8;
                float xs = s_xs[rl];
                float l0 = 0.f, l1 = 0.f;
#pragma unroll
                for (int r = 0; r < RANK; r++) {
                    float xv = s_xa[rl * RANK + r];
                    l0 = fmaf(xv, s_lb[cl * RANK + r], l0);
                    l1 = fmaf(xv, s_lb[(cl + 1) * RANK + r], l1);
                }
                float o0 = (float)c[mf][nf][h * 2 + 0] * xs * ws0 + l0 * lscale;
                float o1 = (float)c[mf][nf][h * 2 + 1] * xs * ws1 + l1 * lscale;
                size_t grow = (size_t)(bm * BM + rl);
                int    gcol = bn * BN + cl;
                *(float2*)(out + grow * N_OUT + gcol) = make_float2(o0, o1);
            }
        }
    }
}

// ---------------------------------------------------------------------------
extern "C" void kernel_launch(void* const* d_in, const int* in_sizes, int n_in,
                              void* d_out, int out_size) {
    const float*  x      = (const float*)d_in[0];
    const void*   w_raw  = d_in[1];
    const float*  wscale = (const float*)d_in[2];
    const float*  lora_a = (const float*)d_in[3];
    const float*  lora_b = (const float*)d_in[4];
    float* out = (float*)d_out;

    int T = in_sizes[0] / K_IN;  // 8192

    detect_init_kernel<<<1, 1>>>();
    detect_kernel<<<16, 256>>>((const int*)w_raw);   // first 4096 words
    pack_kernel<<<(N_OUT * K_IN / 4) / 256, 256>>>(w_raw);

    quant_kernel<<<T, 256>>>(x);
    dim3 g2(T / 256, KSPLIT);
    lora_a_kernel<<<g2, 256>>>(x, lora_a);
    dim3 g3(N_OUT / BN, T / BM);
    gemm_kernel<<<g3, 256>>>(wscale, lora_b, out);
}

// round 3
// speedup vs baseline: 1.0064x; 1.0064x over previous
#include <cuda_runtime.h>
#include <cstdint>

#define T_MAX 8192
#define K_IN  4096
#define N_OUT 4096
#define RANK  8
#define KSPLIT 4

#define BM 128
#define BN 128
#define BK 64
#define SROW 80   // padded smem row stride (bytes): conflict-free LDSM row spread

// Scratch (no allocations allowed)
__device__ int8_t g_xq[(size_t)T_MAX * K_IN];
__device__ float  g_xs[T_MAX];
__device__ float  g_xa[(size_t)KSPLIT * T_MAX * RANK];
__device__ int8_t g_w8[(size_t)N_OUT * K_IN];
__device__ int    g_wmode;   // 1 = weights delivered as int32, 0 = packed int8

// ---------------------------------------------------------------------------
// Kernel 0a: detect weight buffer dtype (int32-promoted vs packed int8).
// ---------------------------------------------------------------------------
__global__ void detect_kernel(const int* __restrict__ w) {
    __shared__ int ok_s;
    if (threadIdx.x == 0) ok_s = 1;
    __syncthreads();
    int v = w[threadIdx.x + blockIdx.x * blockDim.x];
    if (v < -200 || v > 200) atomicAnd(&ok_s, 0);
    __syncthreads();
    if (threadIdx.x == 0 && ok_s == 0) atomicAnd(&g_wmode, 0);
}
__global__ void detect_init_kernel() { g_wmode = 1; }

// Kernel 0b: pack weights into contiguous int8
__global__ __launch_bounds__(256) void pack_kernel(const void* __restrict__ w) {
    size_t gid = (size_t)blockIdx.x * 256 + threadIdx.x;   // one char4 per thread
    if (g_wmode) {
        int4 v = ((const int4*)w)[gid];
        ((char4*)g_w8)[gid] = make_char4((signed char)v.x, (signed char)v.y,
                                         (signed char)v.z, (signed char)v.w);
    } else {
        ((char4*)g_w8)[gid] = ((const char4*)w)[gid];
    }
}

// ---------------------------------------------------------------------------
// Kernel 1: row-wise symmetric int8 quantization of x  (74.5% HBM — done)
// ---------------------------------------------------------------------------
__global__ __launch_bounds__(256) void quant_kernel(const float* __restrict__ x) {
    int row = blockIdx.x;
    int tid = threadIdx.x;
    const float4* xr = (const float4*)(x + (size_t)row * K_IN);
    float4 v[4];
    float m = 0.f;
#pragma unroll
    for (int i = 0; i < 4; i++) {
        v[i] = xr[tid + 256 * i];
        m = fmaxf(m, fmaxf(fmaxf(fabsf(v[i].x), fabsf(v[i].y)),
                           fmaxf(fabsf(v[i].z), fabsf(v[i].w))));
    }
    __shared__ float red[8];
#pragma unroll
    for (int o = 16; o > 0; o >>= 1) m = fmaxf(m, __shfl_xor_sync(0xffffffffu, m, o));
    if ((tid & 31) == 0) red[tid >> 5] = m;
    __syncthreads();
    if (tid < 32) {
        float mm = (tid < 8) ? red[tid] : 0.f;
#pragma unroll
        for (int o = 4; o > 0; o >>= 1) mm = fmaxf(mm, __shfl_xor_sync(0xffffffffu, mm, o));
        if (tid == 0) red[0] = mm;
    }
    __syncthreads();
    m = red[0];
    float scale = m * (1.0f / 127.0f);
    float sc    = fmaxf(scale, 1e-12f);
    float inv   = 1.0f / sc;
    if (tid == 0) g_xs[row] = scale;

    char4* qr = (char4*)(g_xq + (size_t)row * K_IN);
#pragma unroll
    for (int i = 0; i < 4; i++) {
        int qx = __float2int_rn(v[i].x * inv);
        int qy = __float2int_rn(v[i].y * inv);
        int qz = __float2int_rn(v[i].z * inv);
        int qw = __float2int_rn(v[i].w * inv);
        qx = max(-127, min(127, qx)); qy = max(-127, min(127, qy));
        qz = max(-127, min(127, qz)); qw = max(-127, min(127, qw));
        qr[tid + 256 * i] = make_char4((signed char)qx, (signed char)qy,
                                       (signed char)qz, (signed char)qw);
    }
}

// ---------------------------------------------------------------------------
// Kernel 2: xa_part[ks] = x[:, ks-slice] @ A[:, ks-slice]^T   (k-split)
// ---------------------------------------------------------------------------
__global__ __launch_bounds__(256) void lora_a_kernel(const float* __restrict__ x,
                                                     const float* __restrict__ A) {
    int row = blockIdx.x * 256 + threadIdx.x;
    int ks  = blockIdx.y;
    const int KC = K_IN / KSPLIT;            // 1024
    const float4* xr = (const float4*)(x + (size_t)row * K_IN + (size_t)ks * KC);
    float acc[RANK];
#pragma unroll
    for (int r = 0; r < RANK; r++) acc[r] = 0.f;

    const int J = KC / 4;                    // 256
#pragma unroll 4
    for (int j = 0; j < J; j++) {
        float4 xv = xr[j];
        int k = ks * KC + j * 4;
#pragma unroll
        for (int r = 0; r < RANK; r++) {
            float4 av = *(const float4*)(A + (size_t)r * K_IN + k);
            acc[r] = fmaf(xv.x, av.x, acc[r]);
            acc[r] = fmaf(xv.y, av.y, acc[r]);
            acc[r] = fmaf(xv.z, av.z, acc[r]);
            acc[r] = fmaf(xv.w, av.w, acc[r]);
        }
    }
    float* dst = g_xa + ((size_t)ks * T_MAX + row) * RANK;
#pragma unroll
    for (int r = 0; r < RANK; r++) dst[r] = acc[r];
}

// ---------------------------------------------------------------------------
// Kernel 3: int8 GEMM (IMMA m16n8k32, LDSM fragment feed) + fused epilogue
// ---------------------------------------------------------------------------
__device__ __forceinline__ void cp_async16(uint32_t dst, const void* src) {
    asm volatile("cp.async.cg.shared.global [%0], [%1], 16;\n" :: "r"(dst), "l"(src));
}
__device__ __forceinline__ void mma_s8(int* c, const uint32_t* a, const uint32_t* b) {
    asm volatile(
        "mma.sync.aligned.m16n8k32.row.col.s32.s8.s8.s32 "
        "{%0,%1,%2,%3}, {%4,%5,%6,%7}, {%8,%9}, {%0,%1,%2,%3};"
        : "+r"(c[0]), "+r"(c[1]), "+r"(c[2]), "+r"(c[3])
        : "r"(a[0]), "r"(a[1]), "r"(a[2]), "r"(a[3]), "r"(b[0]), "r"(b[1]));
}
__device__ __forceinline__ void ldsm_x4(uint32_t& r0, uint32_t& r1,
                                        uint32_t& r2, uint32_t& r3, uint32_t addr) {
    asm volatile("ldmatrix.sync.aligned.m8n8.x4.shared.b16 {%0,%1,%2,%3}, [%4];"
                 : "=r"(r0), "=r"(r1), "=r"(r2), "=r"(r3) : "r"(addr));
}

__global__ __launch_bounds__(256, 2)
void gemm_kernel(const float* __restrict__ wscale,
                 const float* __restrict__ lora_b,
                 float* __restrict__ out) {
    __shared__ __align__(16) char smem[2 * BM * SROW + 2 * BN * SROW]; // 40960 B
    char* sA = smem;
    char* sB = smem + 2 * BM * SROW;

    int tid  = threadIdx.x;
    int wid  = tid >> 5;
    int lane = tid & 31;
    int gid  = lane >> 2;     // 0..7
    int tid4 = lane & 3;      // 0..3
    int wm = wid & 1;         // 2 warps along M (64 rows each)
    int wn = wid >> 1;        // 4 warps along N (32 cols each)
    int bm = blockIdx.y, bn = blockIdx.x;

    const int8_t* Aglob = g_xq + (size_t)(bm * BM) * K_IN;
    const int8_t* Bglob = g_w8 + (size_t)(bn * BN) * K_IN;

    uint32_t sA_u = (uint32_t)__cvta_generic_to_shared(sA);
    uint32_t sB_u = (uint32_t)__cvta_generic_to_shared(sB);

    // LDSM per-thread address components.
    // A frag (16x32 s8) = 4 8x8-b16 tiles: {rows0-7,k0-15},{rows8-15,k0-15},
    // {rows0-7,k16-31},{rows8-15,k16-31} -> regs a0..a3 (matches mma layout).
    int lane7  = lane & 7;
    int a_row  = ((lane >> 3) & 1) * 8 + lane7;   // row within 16-row frag
    int a_koff = (lane >> 4) * 16;                // 0 or 16
    // B frags for an nf-pair: {n0 rows,k0-15},{n0,k16-31},{n1,k0-15},{n1,k16-31}
    int b_row  = (lane >> 4) * 8 + lane7;         // row within 16-n group
    int b_koff = ((lane >> 3) & 1) * 16;

    int c[4][4][4];
#pragma unroll
    for (int mf = 0; mf < 4; mf++)
#pragma unroll
        for (int nf = 0; nf < 4; nf++)
#pragma unroll
            for (int i = 0; i < 4; i++) c[mf][nf][i] = 0;

#define LOAD_TILE(kt, buf)                                                        \
    {                                                                             \
        int _k0 = (kt) * BK;                                                      \
        _Pragma("unroll")                                                         \
        for (int _u = 0; _u < 2; _u++) {                                          \
            int _idx = tid + 256 * _u;                                            \
            int _row = _idx >> 2;                                                 \
            int _ch  = (_idx & 3) * 16;                                           \
            cp_async16(sA_u + (buf) * (BM * SROW) + _row * SROW + _ch,            \
                       Aglob + (size_t)_row * K_IN + _k0 + _ch);                  \
            cp_async16(sB_u + (buf) * (BN * SROW) + _row * SROW + _ch,            \
                       Bglob + (size_t)_row * K_IN + _k0 + _ch);                  \
        }                                                                         \
        asm volatile("cp.async.commit_group;\n");                                 \
    }

    LOAD_TILE(0, 0);
    asm volatile("cp.async.wait_group 0;\n");
    __syncthreads();

    const int NK = K_IN / BK;  // 64
    for (int kt = 0; kt < NK; kt++) {
        int buf = kt & 1;
        if (kt + 1 < NK) LOAD_TILE(kt + 1, buf ^ 1);

        uint32_t aBase = sA_u + buf * (BM * SROW) + (wm * 64 + a_row) * SROW + a_koff;
        uint32_t bBase = sB_u + buf * (BN * SROW) + (wn * 32 + b_row) * SROW + b_koff;
#pragma unroll
        for (int ks = 0; ks < 2; ks++) {
            int ko = ks * 32;
            uint32_t a[4][4];
#pragma unroll
            for (int mf = 0; mf < 4; mf++)
                ldsm_x4(a[mf][0], a[mf][1], a[mf][2], a[mf][3],
                        aBase + mf * 16 * SROW + ko);
            uint32_t b[4][2];
#pragma unroll
            for (int np = 0; np < 2; np++)
                ldsm_x4(b[2 * np][0], b[2 * np][1], b[2 * np + 1][0], b[2 * np + 1][1],
                        bBase + np * 16 * SROW + ko);
#pragma unroll
            for (int mf = 0; mf < 4; mf++)
#pragma unroll
                for (int nf = 0; nf < 4; nf++)
                    mma_s8(c[mf][nf], a[mf], b[nf]);
        }
        asm volatile("cp.async.wait_group 0;\n");
        __syncthreads();
    }

    // --- epilogue: reuse smem for scales + LoRA operands ---
    float* s_xs = (float*)smem;            // [BM]
    float* s_ws = s_xs + BM;               // [BN]
    float* s_xa = s_ws + BN;               // [BM*RANK]
    float* s_lb = s_xa + BM * RANK;        // [BN*RANK]

    if (tid < BM) s_xs[tid] = g_xs[bm * BM + tid];
    if (tid < BN) s_ws[tid] = wscale[bn * BN + tid];
    for (int i = tid; i < BM * RANK; i += 256) {
        int rl = i >> 3, r = i & 7;
        float s = 0.f;
#pragma unroll
        for (int p = 0; p < KSPLIT; p++)
            s += g_xa[((size_t)p * T_MAX + bm * BM + rl) * RANK + r];
        s_xa[i] = s;
    }
    for (int i = tid; i < BN * RANK; i += 256)
        s_lb[i] = lora_b[(size_t)(bn * BN) * RANK + i];
    __syncthreads();

#pragma unroll
    for (int mf = 0; mf < 4; mf++) {
#pragma unroll
        for (int nf = 0; nf < 4; nf++) {
            int rl0 = wm * 64 + mf * 16 + gid;
            int cl  = wn * 32 + nf * 8 + tid4 * 2;
            float ws0 = s_ws[cl], ws1 = s_ws[cl + 1];
#pragma unroll
            for (int h = 0; h < 2; h++) {
                int rl = rl0 + h * 8;
                float xs = s_xs[rl];
                float l0 = 0.f, l1 = 0.f;
#pragma unroll
                for (int r = 0; r < RANK; r++) {
                    float xv = s_xa[rl * RANK + r];
                    l0 = fmaf(xv, s_lb[cl * RANK + r], l0);
                    l1 = fmaf(xv, s_lb[(cl + 1) * RANK + r], l1);
                }
                float o0 = (float)c[mf][nf][h * 2 + 0] * xs * ws0 + l0;
                float o1 = (float)c[mf][nf][h * 2 + 1] * xs * ws1 + l1;
                size_t grow = (size_t)(bm * BM + rl);
                int    gcol = bn * BN + cl;
                *(float2*)(out + grow * N_OUT + gcol) = make_float2(o0, o1);
            }
        }
    }
}

// ---------------------------------------------------------------------------
extern "C" void kernel_launch(void* const* d_in, const int* in_sizes, int n_in,
                              void* d_out, int out_size) {
    const float*  x      = (const float*)d_in[0];
    const void*   w_raw  = d_in[1];
    const float*  wscale = (const float*)d_in[2];
    const float*  lora_a = (const float*)d_in[3];
    const float*  lora_b = (const float*)d_in[4];
    float* out = (float*)d_out;

    int T = in_sizes[0] / K_IN;  // 8192

    detect_init_kernel<<<1, 1>>>();
    detect_kernel<<<16, 256>>>((const int*)w_raw);
    pack_kernel<<<(N_OUT * K_IN / 4) / 256, 256>>>(w_raw);

    quant_kernel<<<T, 256>>>(x);
    dim3 g2(T / 256, KSPLIT);
    lora_a_kernel<<<g2, 256>>>(x, lora_a);
    dim3 g3(N_OUT / BN, T / BM);
    gemm_kernel<<<g3, 256>>>(wscale, lora_b, out);
}

// round 5
// speedup vs baseline: 1.0144x; 1.0080x over previous
#include <cuda_runtime.h>
#include <cstdint>

#define T_MAX 8192
#define K_IN  4096
#define N_OUT 4096
#define RANK  8
#define KSPLIT 4

#define BM 128
#define BN 128
#define BK 64
#define NKT (K_IN / BK)          // 64
#define STAGES 4
#define SROW 80                  // padded smem row stride (bytes)
#define STAGE_BYTES (2 * BM * SROW)          // A + B per stage = 20480
#define SMEM_TOTAL  (STAGES * STAGE_BYTES)   // 81920

// Scratch (no allocations allowed)
__device__ int8_t g_xq[(size_t)T_MAX * K_IN];
__device__ float  g_xs[T_MAX];
__device__ float  g_xa[(size_t)KSPLIT * T_MAX * RANK];
__device__ int8_t g_w8[(size_t)N_OUT * K_IN];
__device__ int    g_wmode;

// ---------------------------------------------------------------------------
__global__ void detect_kernel(const int* __restrict__ w) {
    __shared__ int ok_s;
    if (threadIdx.x == 0) ok_s = 1;
    __syncthreads();
    int v = w[threadIdx.x + blockIdx.x * blockDim.x];
    if (v < -200 || v > 200) atomicAnd(&ok_s, 0);
    __syncthreads();
    if (threadIdx.x == 0 && ok_s == 0) atomicAnd(&g_wmode, 0);
}
__global__ void detect_init_kernel() { g_wmode = 1; }

__global__ __launch_bounds__(256) void pack_kernel(const void* __restrict__ w) {
    size_t gid = (size_t)blockIdx.x * 256 + threadIdx.x;
    if (g_wmode) {
        int4 v = ((const int4*)w)[gid];
        ((char4*)g_w8)[gid] = make_char4((signed char)v.x, (signed char)v.y,
                                         (signed char)v.z, (signed char)v.w);
    } else {
        ((char4*)g_w8)[gid] = ((const char4*)w)[gid];
    }
}

// ---------------------------------------------------------------------------
__global__ __launch_bounds__(256) void quant_kernel(const float* __restrict__ x) {
    int row = blockIdx.x;
    int tid = threadIdx.x;
    const float4* xr = (const float4*)(x + (size_t)row * K_IN);
    float4 v[4];
    float m = 0.f;
#pragma unroll
    for (int i = 0; i < 4; i++) {
        v[i] = xr[tid + 256 * i];
        m = fmaxf(m, fmaxf(fmaxf(fabsf(v[i].x), fabsf(v[i].y)),
                           fmaxf(fabsf(v[i].z), fabsf(v[i].w))));
    }
    __shared__ float red[8];
#pragma unroll
    for (int o = 16; o > 0; o >>= 1) m = fmaxf(m, __shfl_xor_sync(0xffffffffu, m, o));
    if ((tid & 31) == 0) red[tid >> 5] = m;
    __syncthreads();
    if (tid < 32) {
        float mm = (tid < 8) ? red[tid] : 0.f;
#pragma unroll
        for (int o = 4; o > 0; o >>= 1) mm = fmaxf(mm, __shfl_xor_sync(0xffffffffu, mm, o));
        if (tid == 0) red[0] = mm;
    }
    __syncthreads();
    m = red[0];
    float scale = m * (1.0f / 127.0f);
    float sc    = fmaxf(scale, 1e-12f);
    float inv   = 1.0f / sc;
    if (tid == 0) g_xs[row] = scale;

    char4* qr = (char4*)(g_xq + (size_t)row * K_IN);
#pragma unroll
    for (int i = 0; i < 4; i++) {
        int qx = __float2int_rn(v[i].x * inv);
        int qy = __float2int_rn(v[i].y * inv);
        int qz = __float2int_rn(v[i].z * inv);
        int qw = __float2int_rn(v[i].w * inv);
        qx = max(-127, min(127, qx)); qy = max(-127, min(127, qy));
        qz = max(-127, min(127, qz)); qw = max(-127, min(127, qw));
        qr[tid + 256 * i] = make_char4((signed char)qx, (signed char)qy,
                                       (signed char)qz, (signed char)qw);
    }
}

// ---------------------------------------------------------------------------
__global__ __launch_bounds__(256) void lora_a_kernel(const float* __restrict__ x,
                                                     const float* __restrict__ A) {
    int row = blockIdx.x * 256 + threadIdx.x;
    int ks  = blockIdx.y;
    const int KC = K_IN / KSPLIT;
    const float4* xr = (const float4*)(x + (size_t)row * K_IN + (size_t)ks * KC);
    float acc[RANK];
#pragma unroll
    for (int r = 0; r < RANK; r++) acc[r] = 0.f;
    const int J = KC / 4;
#pragma unroll 4
    for (int j = 0; j < J; j++) {
        float4 xv = xr[j];
        int k = ks * KC + j * 4;
#pragma unroll
        for (int r = 0; r < RANK; r++) {
            float4 av = *(const float4*)(A + (size_t)r * K_IN + k);
            acc[r] = fmaf(xv.x, av.x, acc[r]);
            acc[r] = fmaf(xv.y, av.y, acc[r]);
            acc[r] = fmaf(xv.z, av.z, acc[r]);
            acc[r] = fmaf(xv.w, av.w, acc[r]);
        }
    }
    float* dst = g_xa + ((size_t)ks * T_MAX + row) * RANK;
#pragma unroll
    for (int r = 0; r < RANK; r++) dst[r] = acc[r];
}

// ---------------------------------------------------------------------------
// Kernel 3: int8 GEMM (IMMA m16n8k32, LDSM feed, 4-stage cp.async pipeline)
// ---------------------------------------------------------------------------
__device__ __forceinline__ void cp_async16(uint32_t dst, const void* src) {
    asm volatile("cp.async.cg.shared.global [%0], [%1], 16;\n" :: "r"(dst), "l"(src));
}
__device__ __forceinline__ void mma_s8(int* c, const uint32_t* a, const uint32_t* b) {
    asm volatile(
        "mma.sync.aligned.m16n8k32.row.col.s32.s8.s8.s32 "
        "{%0,%1,%2,%3}, {%4,%5,%6,%7}, {%8,%9}, {%0,%1,%2,%3};"
        : "+r"(c[0]), "+r"(c[1]), "+r"(c[2]), "+r"(c[3])
        : "r"(a[0]), "r"(a[1]), "r"(a[2]), "r"(a[3]), "r"(b[0]), "r"(b[1]));
}
__device__ __forceinline__ void ldsm_x4(uint32_t& r0, uint32_t& r1,
                                        uint32_t& r2, uint32_t& r3, uint32_t addr) {
    asm volatile("ldmatrix.sync.aligned.m8n8.x4.shared.b16 {%0,%1,%2,%3}, [%4];"
                 : "=r"(r0), "=r"(r1), "=r"(r2), "=r"(r3) : "r"(addr));
}

__global__ __launch_bounds__(256, 2)
void gemm_kernel(const float* __restrict__ wscale,
                 const float* __restrict__ lora_b,
                 float* __restrict__ out) {
    extern __shared__ __align__(128) char smem[];
    uint32_t sbase = (uint32_t)__cvta_generic_to_shared(smem);

    int tid  = threadIdx.x;
    int wid  = tid >> 5;
    int lane = tid & 31;
    int gid  = lane >> 2;
    int tid4 = lane & 3;
    int wm = wid & 1;          // 2 warps along M (64 rows)
    int wn = wid >> 1;         // 4 warps along N (32 cols)
    int bm = blockIdx.y, bn = blockIdx.x;

    const int8_t* Aglob = g_xq + (size_t)(bm * BM) * K_IN;
    const int8_t* Bglob = g_w8 + (size_t)(bn * BN) * K_IN;

    // LDSM address components (see round-3 derivation)
    int lane7  = lane & 7;
    int a_row  = ((lane >> 3) & 1) * 8 + lane7;
    int a_koff = (lane >> 4) * 16;
    int b_row  = (lane >> 4) * 8 + lane7;
    int b_koff = ((lane >> 3) & 1) * 16;

    int c[4][4][4];
#pragma unroll
    for (int mf = 0; mf < 4; mf++)
#pragma unroll
        for (int nf = 0; nf < 4; nf++)
#pragma unroll
            for (int i = 0; i < 4; i++) c[mf][nf][i] = 0;

    // stage s: [A 128xSROW][B 128xSROW]
#define LOAD_TILE(t)                                                              \
    {                                                                             \
        int _s  = (t) & (STAGES - 1);                                             \
        int _k0 = (t) * BK;                                                       \
        uint32_t _sa = sbase + _s * STAGE_BYTES;                                  \
        uint32_t _sb = _sa + BM * SROW;                                           \
        _Pragma("unroll")                                                         \
        for (int _u = 0; _u < 2; _u++) {                                          \
            int _idx = tid + 256 * _u;                                            \
            int _row = _idx >> 2;                                                 \
            int _ch  = (_idx & 3) * 16;                                           \
            cp_async16(_sa + _row * SROW + _ch,                                   \
                       Aglob + (size_t)_row * K_IN + _k0 + _ch);                  \
            cp_async16(_sb + _row * SROW + _ch,                                   \
                       Bglob + (size_t)_row * K_IN + _k0 + _ch);                  \
        }                                                                         \
        asm volatile("cp.async.commit_group;\n");                                 \
    }

    // prologue: 3 tiles in flight
    LOAD_TILE(0); LOAD_TILE(1); LOAD_TILE(2);

    for (int kt = 0; kt < NKT; kt++) {
        // tile kt is the 3rd-newest committed group -> wait_group 2 makes it ready
        asm volatile("cp.async.wait_group 2;\n");
        __syncthreads();

        int buf = kt & (STAGES - 1);
        uint32_t aBase = sbase + buf * STAGE_BYTES + (wm * 64 + a_row) * SROW + a_koff;
        uint32_t bBase = sbase + buf * STAGE_BYTES + BM * SROW + (wn * 32 + b_row) * SROW + b_koff;
#pragma unroll
        for (int ks = 0; ks < 2; ks++) {
            int ko = ks * 32;
            uint32_t a[4][4];
#pragma unroll
            for (int mf = 0; mf < 4; mf++)
                ldsm_x4(a[mf][0], a[mf][1], a[mf][2], a[mf][3],
                        aBase + mf * 16 * SROW + ko);
            uint32_t b[4][2];
#pragma unroll
            for (int np = 0; np < 2; np++)
                ldsm_x4(b[2 * np][0], b[2 * np][1], b[2 * np + 1][0], b[2 * np + 1][1],
                        bBase + np * 16 * SROW + ko);
#pragma unroll
            for (int mf = 0; mf < 4; mf++)
#pragma unroll
                for (int nf = 0; nf < 4; nf++)
                    mma_s8(c[mf][nf], a[mf], b[nf]);
        }

        // issue next prefetch AFTER compute: barrier above guarantees every
        // warp finished reading the buffer this overwrites ((kt+3)&3 == (kt-1)&3)
        if (kt + 3 < NKT) {
            LOAD_TILE(kt + 3);
        } else {
            asm volatile("cp.async.commit_group;\n");   // empty group: uniform accounting
        }
    }
    asm volatile("cp.async.wait_group 0;\n");
    __syncthreads();

    // --- epilogue: reuse smem stage 0 for scales + LoRA operands ---
    float* s_xs = (float*)smem;            // [BM]
    float* s_ws = s_xs + BM;               // [BN]
    float* s_xa = s_ws + BN;               // [BM*RANK]
    float* s_lb = s_xa + BM * RANK;        // [BN*RANK]

    if (tid < BM) s_xs[tid] = g_xs[bm * BM + tid];
    if (tid < BN) s_ws[tid] = wscale[bn * BN + tid];
    for (int i = tid; i < BM * RANK; i += 256) {
        int rl = i >> 3, r = i & 7;
        float s = 0.f;
#pragma unroll
        for (int p = 0; p < KSPLIT; p++)
            s += g_xa[((size_t)p * T_MAX + bm * BM + rl) * RANK + r];
        s_xa[i] = s;
    }
    for (int i = tid; i < BN * RANK; i += 256)
        s_lb[i] = lora_b[(size_t)(bn * BN) * RANK + i];
    __syncthreads();

#pragma unroll
    for (int mf = 0; mf < 4; mf++) {
#pragma unroll
        for (int nf = 0; nf < 4; nf++) {
            int rl0 = wm * 64 + mf * 16 + gid;
            int cl  = wn * 32 + nf * 8 + tid4 * 2;
            float ws0 = s_ws[cl], ws1 = s_ws[cl + 1];
#pragma unroll
            for (int h = 0; h < 2; h++) {
                int rl = rl0 + h * 8;
                float xs = s_xs[rl];
                float l0 = 0.f, l1 = 0.f;
#pragma unroll
                for (int r = 0; r < RANK; r++) {
                    float xv = s_xa[rl * RANK + r];
                    l0 = fmaf(xv, s_lb[cl * RANK + r], l0);
                    l1 = fmaf(xv, s_lb[(cl + 1) * RANK + r], l1);
                }
                float o0 = (float)c[mf][nf][h * 2 + 0] * xs * ws0 + l0;
                float o1 = (float)c[mf][nf][h * 2 + 1] * xs * ws1 + l1;
                size_t grow = (size_t)(bm * BM + rl);
                int    gcol = bn * BN + cl;
                *(float2*)(out + grow * N_OUT + gcol) = make_float2(o0, o1);
            }
        }
    }
}

// ---------------------------------------------------------------------------
extern "C" void kernel_launch(void* const* d_in, const int* in_sizes, int n_in,
                              void* d_out, int out_size) {
    const float*  x      = (const float*)d_in[0];
    const void*   w_raw  = d_in[1];
    const float*  wscale = (const float*)d_in[2];
    const float*  lora_a = (const float*)d_in[3];
    const float*  lora_b = (const float*)d_in[4];
    float* out = (float*)d_out;

    int T = in_sizes[0] / K_IN;  // 8192

    cudaFuncSetAttribute(gemm_kernel,
                         cudaFuncAttributeMaxDynamicSharedMemorySize, SMEM_TOTAL);

    detect_init_kernel<<<1, 1>>>();
    detect_kernel<<<16, 256>>>((const int*)w_raw);
    pack_kernel<<<(N_OUT * K_IN / 4) / 256, 256>>>(w_raw);

    quant_kernel<<<T, 256>>>(x);
    dim3 g2(T / 256, KSPLIT);
    lora_a_kernel<<<g2, 256>>>(x, lora_a);
    dim3 g3(N_OUT / BN, T / BM);
    gemm_kernel<<<g3, 256, SMEM_TOTAL>>>(wscale, lora_b, out);
}